// round 13
// baseline (speedup 1.0000x reference)
#include <cuda_runtime.h>
#include <cuda_bf16.h>
#include <math.h>
#include <cstdint>

#define B_ROWS 4096
#define K_COLS 256
#define D_DIM  128
#define BM     64        // x-rows per gemm CTA
#define BKH    64        // hyperplanes per gemm CTA (=> 128 interleaved W rows)
#define MIN_NORM 1e-15f

#define TSTRIDE 136      // bf16 elems per tile row (272 B), conflict-free ldmatrix
#define ROW_BYTES (TSTRIDE * 2)
#define XTILE_BYTES (64 * ROW_BYTES)
#define WTILE_BYTES (128 * ROW_BYTES)

// smem byte offsets (gemm kernel)
#define OFF_XHI  0
#define OFF_XLO  (OFF_XHI + XTILE_BYTES)
#define OFF_WHI  (OFF_XLO + XTILE_BYTES)
#define OFF_WLO  (OFF_WHI + WTILE_BYTES)
#define SMEM_BYTES (OFF_WLO + WTILE_BYTES)    // 104448 B -> 2 CTAs/SM

// ---- global scratch (allocations are forbidden; device globals are not) ----
__device__ uint4  g_xhi[B_ROWS * 16];     // 4096 rows x 256B (128 bf16)
__device__ uint4  g_xlo[B_ROWS * 16];
__device__ uint4  g_whi[512 * 16];        // 512 interleaved rows (2k=p, 2k+1=a)
__device__ uint4  g_wlo[512 * 16];
__device__ float  g_y2[B_ROWS];
__device__ float4 g_kst[K_COLS];          // {p2, pa, beta, 2an}

// ---------------------------------------------------------------------------
__device__ __forceinline__ uint32_t smem_u32(const void* p) {
    uint32_t a;
    asm("{ .reg .u64 t; cvta.to.shared.u64 t, %1; cvt.u32.u64 %0, t; }"
        : "=r"(a) : "l"(p));
    return a;
}

__device__ __forceinline__ void ldsm_x4(uint32_t* r, uint32_t addr) {
    asm volatile("ldmatrix.sync.aligned.m8n8.x4.shared.b16 {%0,%1,%2,%3}, [%4];"
                 : "=r"(r[0]), "=r"(r[1]), "=r"(r[2]), "=r"(r[3]) : "r"(addr));
}

__device__ __forceinline__ void mma_bf16(float* c, const uint32_t* a, const uint32_t* b) {
    asm volatile(
        "mma.sync.aligned.m16n8k16.row.col.f32.bf16.bf16.f32 "
        "{%0,%1,%2,%3}, {%4,%5,%6,%7}, {%8,%9}, {%0,%1,%2,%3};"
        : "+f"(c[0]), "+f"(c[1]), "+f"(c[2]), "+f"(c[3])
        : "r"(a[0]), "r"(a[1]), "r"(a[2]), "r"(a[3]), "r"(b[0]), "r"(b[1]));
}

__device__ __forceinline__ uint32_t prmt7632(uint32_t a, uint32_t b) {
    uint32_t r;
    asm("prmt.b32 %0, %1, %2, 0x7632;" : "=r"(r) : "r"(a), "r"(b));
    return r;
}

// truncation-based fp32 -> bf16 hi/lo split
__device__ __forceinline__ void cvt4t(const float4 v, uint2& hi, uint2& lo) {
    uint32_t u0 = __float_as_uint(v.x), u1 = __float_as_uint(v.y);
    uint32_t u2 = __float_as_uint(v.z), u3 = __float_as_uint(v.w);
    hi.x = prmt7632(u0, u1);
    hi.y = prmt7632(u2, u3);
    float l0 = v.x - __uint_as_float(u0 & 0xFFFF0000u);
    float l1 = v.y - __uint_as_float(u1 & 0xFFFF0000u);
    float l2 = v.z - __uint_as_float(u2 & 0xFFFF0000u);
    float l3 = v.w - __uint_as_float(u3 & 0xFFFF0000u);
    lo.x = prmt7632(__float_as_uint(l0), __float_as_uint(l1));
    lo.y = prmt7632(__float_as_uint(l2), __float_as_uint(l3));
}

__device__ __forceinline__ float fast_asinh(float z) {
    float az = fabsf(z);
    float u  = fmaf(az, az, 1.f);
    float t;
    asm("sqrt.approx.f32 %0, %1;" : "=f"(t) : "f"(u));
    float r = __logf(az + t);
    return copysignf(r, z);
}

__device__ __forceinline__ float mobius_epi(float px, float xa, float y2, float4 kc) {
    const float p2 = kc.x, pa = kc.y, beta = kc.z, an2 = kc.w;
    float t     = fmaf(-2.f, px, 1.f);
    float alpha = t + y2;
    float den   = fmaf(p2, y2, t);
    float num   = fmaf(beta, xa, -alpha * pa);
    float b2y2  = beta * beta * y2;
    float e2    = fmaf(alpha * p2, alpha, b2y2);
    float e3    = fmaf(-beta, t, beta);
    float ms2   = fmaf(-alpha, e3, e2);
    float g     = fmaf(den, den, -ms2);
    float dn    = fmaxf(an2 * g, MIN_NORM);
    float z     = __fdividef(4.f * num * den, dn);
    return an2 * fast_asinh(z);
}

// ---------------------------------------------------------------------------
// Kernel 1: convert X/W to bf16 hi/lo scratch + y2 + per-k stats
// blocks 0..127: X (32 rows each). blocks 128..143: W (32 rows each) + stats.
// ---------------------------------------------------------------------------
__global__ void __launch_bounds__(256)
mobius_prep_kernel(const float* __restrict__ x,
                   const float* __restrict__ gp,
                   const float* __restrict__ ga) {
    const int tid  = threadIdx.x;
    const int lane = tid & 31;
    const int bx   = blockIdx.x;

    if (bx < 128) {
        const int rb = bx * 32;
        const float4* x4 = (const float4*)x;
#pragma unroll
        for (int i = 0; i < 4; i++) {
            int idx = tid + i * 256;
            int row = rb + (idx >> 5);          // warp per row
            int c4  = idx & 31;
            float4 v = x4[row * 32 + c4];
            uint2 hi, lo;
            cvt4t(v, hi, lo);
            ((uint2*)g_xhi)[row * 32 + c4] = hi;
            ((uint2*)g_xlo)[row * 32 + c4] = lo;
            float s = fmaf(v.x, v.x, fmaf(v.y, v.y, fmaf(v.z, v.z, v.w * v.w)));
            s += __shfl_xor_sync(0xffffffffu, s, 1);
            s += __shfl_xor_sync(0xffffffffu, s, 2);
            s += __shfl_xor_sync(0xffffffffu, s, 4);
            s += __shfl_xor_sync(0xffffffffu, s, 8);
            s += __shfl_xor_sync(0xffffffffu, s, 16);
            if (lane == 0) g_y2[row] = s;
        }
    } else {
        const int wb = (bx - 128) * 32;         // W row base (interleaved rows)
#pragma unroll
        for (int i = 0; i < 4; i++) {
            int idx = tid + i * 256;
            int row = wb + (idx >> 5);          // 0..511
            int c4  = idx & 31;
            int kk  = row >> 1;
            const float4* src = (const float4*)(((row & 1) ? ga : gp) + (size_t)kk * D_DIM);
            float4 v = src[c4];
            uint2 hi, lo;
            cvt4t(v, hi, lo);
            ((uint2*)g_whi)[row * 32 + c4] = hi;
            ((uint2*)g_wlo)[row * 32 + c4] = lo;
        }
        // stats: 16 threads per k, 16 k per CTA
        {
            const int k0  = (bx - 128) * 16;
            const int kk  = k0 + (tid >> 4);
            const int seg = tid & 15;
            const float4* pr = (const float4*)(gp + (size_t)kk * D_DIM) + seg * 2;
            const float4* ar = (const float4*)(ga + (size_t)kk * D_DIM) + seg * 2;
            float p2 = 0.f, pa = 0.f, a2 = 0.f;
#pragma unroll
            for (int i = 0; i < 2; i++) {
                float4 pv = pr[i], av = ar[i];
                p2 = fmaf(pv.x, pv.x, fmaf(pv.y, pv.y, fmaf(pv.z, pv.z, fmaf(pv.w, pv.w, p2))));
                pa = fmaf(pv.x, av.x, fmaf(pv.y, av.y, fmaf(pv.z, av.z, fmaf(pv.w, av.w, pa))));
                a2 = fmaf(av.x, av.x, fmaf(av.y, av.y, fmaf(av.z, av.z, fmaf(av.w, av.w, a2))));
            }
            p2 += __shfl_xor_sync(0xffffffffu, p2, 1);
            p2 += __shfl_xor_sync(0xffffffffu, p2, 2);
            p2 += __shfl_xor_sync(0xffffffffu, p2, 4);
            p2 += __shfl_xor_sync(0xffffffffu, p2, 8);
            pa += __shfl_xor_sync(0xffffffffu, pa, 1);
            pa += __shfl_xor_sync(0xffffffffu, pa, 2);
            pa += __shfl_xor_sync(0xffffffffu, pa, 4);
            pa += __shfl_xor_sync(0xffffffffu, pa, 8);
            a2 += __shfl_xor_sync(0xffffffffu, a2, 1);
            a2 += __shfl_xor_sync(0xffffffffu, a2, 2);
            a2 += __shfl_xor_sync(0xffffffffu, a2, 4);
            a2 += __shfl_xor_sync(0xffffffffu, a2, 8);
            if (seg == 0) {
                float an = fmaxf(sqrtf(a2), MIN_NORM);
                g_kst[kk] = make_float4(p2, pa, 1.f - p2, 2.f * an);
            }
        }
    }
}

// ---------------------------------------------------------------------------
// Kernel 2: pure bf16 GEMM (3-pass split) + Mobius epilogue.
// BM=64 x BKH=64 per CTA, 256 threads, 2 CTAs/SM.
// ---------------------------------------------------------------------------
extern __shared__ char smem[];

__global__ void __launch_bounds__(256, 2)
mobius_gemm_kernel(float* __restrict__ out) {
    const uint32_t sb  = smem_u32(smem);
    const int tid  = threadIdx.x;
    const int wid  = tid >> 5;
    const int lane = tid & 31;
    const int kb   = blockIdx.x * BKH;
    const int bb   = blockIdx.y * BM;

    // ---- copy bf16 tiles from L2-hot scratch into swizzle-free smem -------
    // X: 64 rows x 16 chunks (hi,lo) = 4+4 iters; W: 128 rows = 8+8 iters.
#pragma unroll
    for (int i = 0; i < 4; i++) {
        int idx = tid + i * 256;
        int row = idx >> 4;
        int c   = idx & 15;
        uint32_t off = (uint32_t)(row * ROW_BYTES + c * 16);
        *(uint4*)(smem + OFF_XHI + off) = g_xhi[(bb + row) * 16 + c];
        *(uint4*)(smem + OFF_XLO + off) = g_xlo[(bb + row) * 16 + c];
    }
#pragma unroll
    for (int i = 0; i < 8; i++) {
        int idx = tid + i * 256;
        int row = idx >> 4;
        int c   = idx & 15;
        uint32_t off = (uint32_t)(row * ROW_BYTES + c * 16);
        *(uint4*)(smem + OFF_WHI + off) = g_whi[(2 * kb + row) * 16 + c];
        *(uint4*)(smem + OFF_WLO + off) = g_wlo[(2 * kb + row) * 16 + c];
    }
    __syncthreads();

    // ---- warp tiling: 8 warps, warp tile 16 rows x 64 W-cols --------------
    const int wm = wid & 3;
    const int wn = wid >> 2;
    const int rm = wm * 16;
    const int cn = wn * 64;

    const int a_row = lane & 15;
    const int a_kh  = (lane >> 4) * 8;
    const int b_g   = lane >> 3;
    const int b_row = lane & 7;
    const int b_joff = (b_g >> 1);
    const int b_kh  = (b_g & 1) * 8;

    float acc[8][4];
#pragma unroll
    for (int j = 0; j < 8; j++)
#pragma unroll
        for (int q = 0; q < 4; q++) acc[j][q] = 0.f;

#pragma unroll
    for (int ks = 0; ks < 8; ks++) {
        const int kk = ks * 16;
        uint32_t Ahi[4], Alo[4], Bhi[8][2], Blo[8][2];
        {
            uint32_t aoff = (uint32_t)((rm + a_row) * ROW_BYTES + (kk + a_kh) * 2);
            ldsm_x4(Ahi, sb + OFF_XHI + aoff);
            ldsm_x4(Alo, sb + OFF_XLO + aoff);
        }
#pragma unroll
        for (int jp = 0; jp < 4; jp++) {
            uint32_t boff = (uint32_t)((cn + (2 * jp + b_joff) * 8 + b_row) * ROW_BYTES
                                       + (kk + b_kh) * 2);
            uint32_t r[4];
            ldsm_x4(r, sb + OFF_WHI + boff);
            Bhi[2 * jp][0] = r[0]; Bhi[2 * jp][1] = r[1];
            Bhi[2 * jp + 1][0] = r[2]; Bhi[2 * jp + 1][1] = r[3];
            ldsm_x4(r, sb + OFF_WLO + boff);
            Blo[2 * jp][0] = r[0]; Blo[2 * jp][1] = r[1];
            Blo[2 * jp + 1][0] = r[2]; Blo[2 * jp + 1][1] = r[3];
        }
#pragma unroll
        for (int j = 0; j < 8; j++) {
            mma_bf16(acc[j], Ahi, Bhi[j]);
            mma_bf16(acc[j], Ahi, Blo[j]);
            mma_bf16(acc[j], Alo, Bhi[j]);
        }
    }

    // ---- epilogue: scalars straight from L2-hot globals -------------------
    const int l4 = lane >> 2;
    const int lm = lane & 3;
    const int r0 = rm + l4;
    const int r1 = r0 + 8;
    const float y20 = g_y2[bb + r0];
    const float y21 = g_y2[bb + r1];
    float* o0 = out + (size_t)(bb + r0) * K_COLS + kb;
    float* o1 = out + (size_t)(bb + r1) * K_COLS + kb;
#pragma unroll
    for (int j = 0; j < 8; j++) {
        const int kl = wn * 32 + j * 4 + lm;
        const float4 kc = g_kst[kb + kl];
        o0[kl] = mobius_epi(acc[j][0], acc[j][1], y20, kc);
        o1[kl] = mobius_epi(acc[j][2], acc[j][3], y21, kc);
    }
}

// ---------------------------------------------------------------------------
extern "C" void kernel_launch(void* const* d_in, const int* in_sizes, int n_in,
                              void* d_out, int out_size) {
    const float* x = (const float*)d_in[0];   // (4096, 128)
    const float* p = (const float*)d_in[1];   // (256, 128)
    const float* a = (const float*)d_in[2];   // (256, 128)
    float* out = (float*)d_out;               // (4096, 256)

    cudaFuncSetAttribute(mobius_gemm_kernel,
                         cudaFuncAttributeMaxDynamicSharedMemorySize, SMEM_BYTES);

    mobius_prep_kernel<<<144, 256>>>(x, p, a);
    dim3 grid(K_COLS / BKH, B_ROWS / BM);     // (4, 64) = 256 CTAs, 2/SM
    mobius_gemm_kernel<<<grid, 256, SMEM_BYTES>>>(out);
}

// round 14
// speedup vs baseline: 1.1265x; 1.1265x over previous
#include <cuda_runtime.h>
#include <cuda_bf16.h>
#include <math.h>
#include <cstdint>

#define B_ROWS 4096
#define K_COLS 256
#define D_DIM  128
#define BM     128       // x-rows per CTA
#define BKH    64        // hyperplanes per CTA (=> 128 interleaved W rows)
#define THREADS 1024
#define MIN_NORM 1e-15f

#define TSTRIDE 136      // bf16 elems per tile row (272 B), conflict-free ldmatrix
#define ROW_BYTES (TSTRIDE * 2)
#define TILE_BYTES (128 * ROW_BYTES)

// smem byte offsets
#define OFF_Y2   0                       // 128 f32
#define OFF_KST  512                     // 64 x float4 {p2, pa, beta, 2an}
#define OFF_XHI  2048
#define OFF_XLO  (OFF_XHI + TILE_BYTES)
#define OFF_WHI  (OFF_XLO + TILE_BYTES)
#define OFF_WLO  (OFF_WHI + TILE_BYTES)
#define SMEM_BYTES (OFF_WLO + TILE_BYTES)   // ~141 KB, 1 CTA/SM

// ---------------------------------------------------------------------------
__device__ __forceinline__ uint32_t smem_u32(const void* p) {
    uint32_t a;
    asm("{ .reg .u64 t; cvta.to.shared.u64 t, %1; cvt.u32.u64 %0, t; }"
        : "=r"(a) : "l"(p));
    return a;
}

__device__ __forceinline__ void ldsm_x4(uint32_t* r, uint32_t addr) {
    asm volatile("ldmatrix.sync.aligned.m8n8.x4.shared.b16 {%0,%1,%2,%3}, [%4];"
                 : "=r"(r[0]), "=r"(r[1]), "=r"(r[2]), "=r"(r[3]) : "r"(addr));
}

__device__ __forceinline__ void mma_bf16(float* c, const uint32_t* a, const uint32_t* b) {
    asm volatile(
        "mma.sync.aligned.m16n8k16.row.col.f32.bf16.bf16.f32 "
        "{%0,%1,%2,%3}, {%4,%5,%6,%7}, {%8,%9}, {%0,%1,%2,%3};"
        : "+f"(c[0]), "+f"(c[1]), "+f"(c[2]), "+f"(c[3])
        : "r"(a[0]), "r"(a[1]), "r"(a[2]), "r"(a[3]), "r"(b[0]), "r"(b[1]));
}

__device__ __forceinline__ uint32_t prmt7632(uint32_t a, uint32_t b) {
    uint32_t r;
    asm("prmt.b32 %0, %1, %2, 0x7632;" : "=r"(r) : "r"(a), "r"(b));
    return r;
}

// truncation-based fp32 -> bf16 hi/lo split (all fixed-lat ALU ops)
__device__ __forceinline__ void cvt4t(const float4 v, uint2& hi, uint2& lo) {
    uint32_t u0 = __float_as_uint(v.x), u1 = __float_as_uint(v.y);
    uint32_t u2 = __float_as_uint(v.z), u3 = __float_as_uint(v.w);
    hi.x = prmt7632(u0, u1);
    hi.y = prmt7632(u2, u3);
    float l0 = v.x - __uint_as_float(u0 & 0xFFFF0000u);
    float l1 = v.y - __uint_as_float(u1 & 0xFFFF0000u);
    float l2 = v.z - __uint_as_float(u2 & 0xFFFF0000u);
    float l3 = v.w - __uint_as_float(u3 & 0xFFFF0000u);
    lo.x = prmt7632(__float_as_uint(l0), __float_as_uint(l1));
    lo.y = prmt7632(__float_as_uint(l2), __float_as_uint(l3));
}

// fast asinh: sign * log(|z| + sqrt(z^2+1))
__device__ __forceinline__ float fast_asinh(float z) {
    float az = fabsf(z);
    float u  = fmaf(az, az, 1.f);
    float t;
    asm("sqrt.approx.f32 %0, %1;" : "=f"(t) : "f"(u));
    float r = __logf(az + t);
    return copysignf(r, z);
}

// single-division Mobius epilogue; kc = {p2, pa, beta, 2an}
__device__ __forceinline__ float mobius_epi(float px, float xa, float y2, float4 kc) {
    const float p2 = kc.x, pa = kc.y, beta = kc.z, an2 = kc.w;
    float t     = fmaf(-2.f, px, 1.f);          // 1 - 2px
    float alpha = t + y2;
    float den   = fmaf(p2, y2, t);              // den_m
    float num   = fmaf(beta, xa, -alpha * pa);  // beta*xa - alpha*pa
    float b2y2  = beta * beta * y2;
    float e2    = fmaf(alpha * p2, alpha, b2y2);
    float e3    = fmaf(-beta, t, beta);         // 2*beta*px
    float ms2   = fmaf(-alpha, e3, e2);
    float g     = fmaf(den, den, -ms2);
    float dn    = fmaxf(an2 * g, MIN_NORM);
    float z     = __fdividef(4.f * num * den, dn);
    return an2 * fast_asinh(z);
}

// ---------------------------------------------------------------------------
extern __shared__ char smem[];

__global__ void __launch_bounds__(THREADS, 1)
mobius_mlr_mma_kernel(const float* __restrict__ x,
                      const float* __restrict__ gp,
                      const float* __restrict__ ga,
                      float* __restrict__ out) {
    const uint32_t sb  = smem_u32(smem);
    const int tid  = threadIdx.x;
    const int wid  = tid >> 5;           // 0..31
    const int lane = tid & 31;
    const int kb   = blockIdx.x * BKH;
    const int bb   = blockIdx.y * BM;

    float*  y2s = (float*)(smem + OFF_Y2);
    float4* kst = (float4*)(smem + OFF_KST);

    // ---- load X: warp-per-row, 4 rows per warp (w, w+32, w+64, w+96) ------
    const float4* x4 = (const float4*)(x + (size_t)bb * D_DIM);
    float4 Xv[4];
#pragma unroll
    for (int i = 0; i < 4; i++) {
        int row = wid + 32 * i;
        Xv[i] = x4[row * 32 + lane];
    }

    // ---- load W: half-warp per row (p in lanes 0-15, a in 16-31), 2 iters -
    float4 Wv0[2], Wv1[2];
#pragma unroll
    for (int i = 0; i < 2; i++) {
        int row = 2 * wid + 64 * i + (lane >> 4);   // 0..127
        int kk  = kb + (row >> 1);
        const float4* src = (const float4*)(((row & 1) ? ga : gp) + (size_t)kk * D_DIM);
        Wv0[i] = src[lane & 15];
        Wv1[i] = src[(lane & 15) + 16];
    }

    // ---- convert X + y2 (full-warp reduce per row) ------------------------
#pragma unroll
    for (int i = 0; i < 4; i++) {
        int row = wid + 32 * i;
        uint2 hi, lo;
        cvt4t(Xv[i], hi, lo);
        uint32_t off = (uint32_t)(row * ROW_BYTES + lane * 8);
        *(uint2*)(smem + OFF_XHI + off) = hi;
        *(uint2*)(smem + OFF_XLO + off) = lo;
        float4 v = Xv[i];
        float s = fmaf(v.x, v.x, fmaf(v.y, v.y, fmaf(v.z, v.z, v.w * v.w)));
        s += __shfl_xor_sync(0xffffffffu, s, 1);
        s += __shfl_xor_sync(0xffffffffu, s, 2);
        s += __shfl_xor_sync(0xffffffffu, s, 4);
        s += __shfl_xor_sync(0xffffffffu, s, 8);
        s += __shfl_xor_sync(0xffffffffu, s, 16);
        if (lane == 0) y2s[row] = s;
    }

    // ---- convert W + per-k stats from registers ---------------------------
#pragma unroll
    for (int i = 0; i < 2; i++) {
        int row = 2 * wid + 64 * i + (lane >> 4);
        int c4  = lane & 15;
        uint2 hi, lo;
        cvt4t(Wv0[i], hi, lo);
        uint32_t off = (uint32_t)(row * ROW_BYTES + c4 * 8);
        *(uint2*)(smem + OFF_WHI + off) = hi;
        *(uint2*)(smem + OFF_WLO + off) = lo;
        cvt4t(Wv1[i], hi, lo);
        *(uint2*)(smem + OFF_WHI + off + 128) = hi;
        *(uint2*)(smem + OFF_WLO + off + 128) = lo;

        float4 a = Wv0[i], b = Wv1[i];
        float s = fmaf(a.x, a.x, fmaf(a.y, a.y, fmaf(a.z, a.z, a.w * a.w)));
        s = fmaf(b.x, b.x, fmaf(b.y, b.y, fmaf(b.z, b.z, fmaf(b.w, b.w, s))));
        float q0 = __shfl_xor_sync(0xffffffffu, a.x, 16);
        float q1 = __shfl_xor_sync(0xffffffffu, a.y, 16);
        float q2 = __shfl_xor_sync(0xffffffffu, a.z, 16);
        float q3 = __shfl_xor_sync(0xffffffffu, a.w, 16);
        float r0 = __shfl_xor_sync(0xffffffffu, b.x, 16);
        float r1 = __shfl_xor_sync(0xffffffffu, b.y, 16);
        float r2 = __shfl_xor_sync(0xffffffffu, b.z, 16);
        float r3 = __shfl_xor_sync(0xffffffffu, b.w, 16);
        float pa = fmaf(a.x, q0, fmaf(a.y, q1, fmaf(a.z, q2, a.w * q3)));
        pa = fmaf(b.x, r0, fmaf(b.y, r1, fmaf(b.z, r2, fmaf(b.w, r3, pa))));
        s  += __shfl_xor_sync(0xffffffffu, s, 1);
        s  += __shfl_xor_sync(0xffffffffu, s, 2);
        s  += __shfl_xor_sync(0xffffffffu, s, 4);
        s  += __shfl_xor_sync(0xffffffffu, s, 8);
        pa += __shfl_xor_sync(0xffffffffu, pa, 1);
        pa += __shfl_xor_sync(0xffffffffu, pa, 2);
        pa += __shfl_xor_sync(0xffffffffu, pa, 4);
        pa += __shfl_xor_sync(0xffffffffu, pa, 8);
        float s_opp = __shfl_xor_sync(0xffffffffu, s, 16);   // a2 -> low lanes
        if (lane == 0) {
            int k = wid + 32 * i;                // CTA-local k (0..63)
            float p2 = s, a2 = s_opp;
            float an = fmaxf(sqrtf(a2), MIN_NORM);
            kst[k] = make_float4(p2, pa, 1.f - p2, 2.f * an);
        }
    }
    __syncthreads();

    // ---- warp tiling: 32 warps, warp tile 16 rows x 32 W-cols -------------
    const int wm = wid & 7;          // 8 row blocks of 16
    const int wn = wid >> 3;         // 4 col blocks of 32 W-cols
    const int rm = wm * 16;
    const int cn = wn * 32;

    const int a_row = lane & 15;
    const int a_kh  = (lane >> 4) * 8;
    const int b_g   = lane >> 3;
    const int b_row = lane & 7;
    const int b_joff = (b_g >> 1);
    const int b_kh  = (b_g & 1) * 8;

    float acc[4][4];
#pragma unroll
    for (int j = 0; j < 4; j++)
#pragma unroll
        for (int q = 0; q < 4; q++) acc[j][q] = 0.f;

#pragma unroll
    for (int ks = 0; ks < 8; ks++) {
        const int kk = ks * 16;
        uint32_t Ahi[4], Alo[4], Bhi[4][2], Blo[4][2];
        {
            uint32_t aoff = (uint32_t)((rm + a_row) * ROW_BYTES + (kk + a_kh) * 2);
            ldsm_x4(Ahi, sb + OFF_XHI + aoff);
            ldsm_x4(Alo, sb + OFF_XLO + aoff);
        }
#pragma unroll
        for (int jp = 0; jp < 2; jp++) {
            uint32_t boff = (uint32_t)((cn + (2 * jp + b_joff) * 8 + b_row) * ROW_BYTES
                                       + (kk + b_kh) * 2);
            uint32_t r[4];
            ldsm_x4(r, sb + OFF_WHI + boff);
            Bhi[2 * jp][0] = r[0]; Bhi[2 * jp][1] = r[1];
            Bhi[2 * jp + 1][0] = r[2]; Bhi[2 * jp + 1][1] = r[3];
            ldsm_x4(r, sb + OFF_WLO + boff);
            Blo[2 * jp][0] = r[0]; Blo[2 * jp][1] = r[1];
            Blo[2 * jp + 1][0] = r[2]; Blo[2 * jp + 1][1] = r[3];
        }
#pragma unroll
        for (int j = 0; j < 4; j++) {
            mma_bf16(acc[j], Ahi, Bhi[j]);
            mma_bf16(acc[j], Ahi, Blo[j]);
            mma_bf16(acc[j], Alo, Bhi[j]);
        }
    }

    // ---- epilogue: 8 outputs per thread -----------------------------------
    const int l4 = lane >> 2;
    const int lm = lane & 3;
    const int r0 = rm + l4;
    const int r1 = r0 + 8;
    const float y20 = y2s[r0];
    const float y21 = y2s[r1];
    float* o0 = out + (size_t)(bb + r0) * K_COLS + kb;
    float* o1 = out + (size_t)(bb + r1) * K_COLS + kb;
#pragma unroll
    for (int j = 0; j < 4; j++) {
        const int kl = wn * 16 + j * 4 + lm;
        const float4 kc = kst[kl];
        o0[kl] = mobius_epi(acc[j][0], acc[j][1], y20, kc);
        o1[kl] = mobius_epi(acc[j][2], acc[j][3], y21, kc);
    }
}

// ---------------------------------------------------------------------------
extern "C" void kernel_launch(void* const* d_in, const int* in_sizes, int n_in,
                              void* d_out, int out_size) {
    const float* x = (const float*)d_in[0];   // (4096, 128)
    const float* p = (const float*)d_in[1];   // (256, 128)
    const float* a = (const float*)d_in[2];   // (256, 128)
    float* out = (float*)d_out;               // (4096, 256)

    cudaFuncSetAttribute(mobius_mlr_mma_kernel,
                         cudaFuncAttributeMaxDynamicSharedMemorySize, SMEM_BYTES);

    dim3 grid(K_COLS / BKH, B_ROWS / BM);     // (4, 32) = 128 CTAs, one wave
    mobius_mlr_mma_kernel<<<grid, THREADS, SMEM_BYTES>>>(x, p, a, out);
}

// round 15
// speedup vs baseline: 1.1830x; 1.0501x over previous
#include <cuda_runtime.h>
#include <cuda_bf16.h>
#include <math.h>
#include <cstdint>

#define B_ROWS 4096
#define K_COLS 256
#define D_DIM  128
#define BM     128       // x-rows per CTA
#define BKH    64        // hyperplanes per CTA (=> 128 interleaved W rows)
#define THREADS 512
#define MIN_NORM 1e-15f

#define TSTRIDE 136      // bf16 elems per tile row (272 B), conflict-free ldmatrix
#define ROW_BYTES (TSTRIDE * 2)
#define TILE_BYTES (128 * ROW_BYTES)

// smem byte offsets
#define OFF_Y2   0                       // 128 f32
#define OFF_KST  512                     // 64 x float4 {p2, pa, beta, 2an}
#define OFF_XHI  2048
#define OFF_XLO  (OFF_XHI + TILE_BYTES)
#define OFF_WHI  (OFF_XLO + TILE_BYTES)
#define OFF_WLO  (OFF_WHI + TILE_BYTES)
#define SMEM_BYTES (OFF_WLO + TILE_BYTES)

// ---------------------------------------------------------------------------
__device__ __forceinline__ uint32_t smem_u32(const void* p) {
    uint32_t a;
    asm("{ .reg .u64 t; cvta.to.shared.u64 t, %1; cvt.u32.u64 %0, t; }"
        : "=r"(a) : "l"(p));
    return a;
}

__device__ __forceinline__ void ldsm_x4(uint32_t* r, uint32_t addr) {
    asm volatile("ldmatrix.sync.aligned.m8n8.x4.shared.b16 {%0,%1,%2,%3}, [%4];"
                 : "=r"(r[0]), "=r"(r[1]), "=r"(r[2]), "=r"(r[3]) : "r"(addr));
}

__device__ __forceinline__ void mma_bf16(float* c, const uint32_t* a, const uint32_t* b) {
    asm volatile(
        "mma.sync.aligned.m16n8k16.row.col.f32.bf16.bf16.f32 "
        "{%0,%1,%2,%3}, {%4,%5,%6,%7}, {%8,%9}, {%0,%1,%2,%3};"
        : "+f"(c[0]), "+f"(c[1]), "+f"(c[2]), "+f"(c[3])
        : "r"(a[0]), "r"(a[1]), "r"(a[2]), "r"(a[3]), "r"(b[0]), "r"(b[1]));
}

__device__ __forceinline__ uint32_t prmt7632(uint32_t a, uint32_t b) {
    uint32_t r;
    asm("prmt.b32 %0, %1, %2, 0x7632;" : "=r"(r) : "r"(a), "r"(b));
    return r;
}

// truncation-based fp32 -> bf16 hi/lo split (all fixed-lat ALU ops)
__device__ __forceinline__ void cvt4t(const float4 v, uint2& hi, uint2& lo) {
    uint32_t u0 = __float_as_uint(v.x), u1 = __float_as_uint(v.y);
    uint32_t u2 = __float_as_uint(v.z), u3 = __float_as_uint(v.w);
    hi.x = prmt7632(u0, u1);
    hi.y = prmt7632(u2, u3);
    float l0 = v.x - __uint_as_float(u0 & 0xFFFF0000u);
    float l1 = v.y - __uint_as_float(u1 & 0xFFFF0000u);
    float l2 = v.z - __uint_as_float(u2 & 0xFFFF0000u);
    float l3 = v.w - __uint_as_float(u3 & 0xFFFF0000u);
    lo.x = prmt7632(__float_as_uint(l0), __float_as_uint(l1));
    lo.y = prmt7632(__float_as_uint(l2), __float_as_uint(l3));
}

// fast asinh: sign * log(|z| + sqrt(z^2+1))
__device__ __forceinline__ float fast_asinh(float z) {
    float az = fabsf(z);
    float u  = fmaf(az, az, 1.f);
    float t;
    asm("sqrt.approx.f32 %0, %1;" : "=f"(t) : "f"(u));
    float r = __logf(az + t);
    return copysignf(r, z);
}

// single-division Mobius epilogue; kc = {p2, pa, beta, 2an}
__device__ __forceinline__ float mobius_epi(float px, float xa, float y2, float4 kc) {
    const float p2 = kc.x, pa = kc.y, beta = kc.z, an2 = kc.w;
    float t     = fmaf(-2.f, px, 1.f);          // 1 - 2px
    float alpha = t + y2;
    float den   = fmaf(p2, y2, t);              // den_m
    float num   = fmaf(beta, xa, -alpha * pa);  // beta*xa - alpha*pa
    float b2y2  = beta * beta * y2;
    float e2    = fmaf(alpha * p2, alpha, b2y2);
    float e3    = fmaf(-beta, t, beta);         // 2*beta*px
    float ms2   = fmaf(-alpha, e3, e2);
    float g     = fmaf(den, den, -ms2);
    float dn    = fmaxf(an2 * g, MIN_NORM);
    float z     = __fdividef(4.f * num * den, dn);
    return an2 * fast_asinh(z);
}

// ---------------------------------------------------------------------------
extern __shared__ char smem[];

__global__ void __launch_bounds__(THREADS, 1)
mobius_mlr_mma_kernel(const float* __restrict__ x,
                      const float* __restrict__ gp,
                      const float* __restrict__ ga,
                      float* __restrict__ out) {
    const uint32_t sb  = smem_u32(smem);
    const int tid  = threadIdx.x;
    const int wid  = tid >> 5;
    const int lane = tid & 31;
    const int kb   = blockIdx.x * BKH;
    const int bb   = blockIdx.y * BM;

    float*  y2s = (float*)(smem + OFF_Y2);
    float4* kst = (float4*)(smem + OFF_KST);

    const float4* x4 = (const float4*)(x + (size_t)bb * D_DIM);

    // warp tiling constants (16 warps, warp tile 32 rows x 32 W-cols)
    const int wm = wid & 3;
    const int wn = wid >> 2;
    const int rm = wm * 32;
    const int cn = wn * 32;

    const int a_row = lane & 15;
    const int a_kh  = (lane >> 4) * 8;
    const int b_g   = lane >> 3;
    const int b_row = lane & 7;
    const int b_joff = (b_g >> 1);
    const int b_kh  = (b_g & 1) * 8;

    float acc[2][4][4];
#pragma unroll
    for (int ma = 0; ma < 2; ma++)
#pragma unroll
        for (int j = 0; j < 4; j++)
#pragma unroll
            for (int q = 0; q < 4; q++) acc[ma][j][q] = 0.f;

    // double-buffered fragments
    uint32_t pAhi[2][2][4], pAlo[2][2][4], pBhi[2][4][2], pBlo[2][4][2];

    auto load_frags = [&](int buf, int ks) {
        const int kk = ks * 16;
#pragma unroll
        for (int ma = 0; ma < 2; ma++) {
            uint32_t aoff = (uint32_t)((rm + ma * 16 + a_row) * ROW_BYTES
                                       + (kk + a_kh) * 2);
            ldsm_x4(pAhi[buf][ma], sb + OFF_XHI + aoff);
            ldsm_x4(pAlo[buf][ma], sb + OFF_XLO + aoff);
        }
#pragma unroll
        for (int jp = 0; jp < 2; jp++) {
            uint32_t boff = (uint32_t)((cn + (2 * jp + b_joff) * 8 + b_row) * ROW_BYTES
                                       + (kk + b_kh) * 2);
            uint32_t r[4];
            ldsm_x4(r, sb + OFF_WHI + boff);
            pBhi[buf][2 * jp][0] = r[0]; pBhi[buf][2 * jp][1] = r[1];
            pBhi[buf][2 * jp + 1][0] = r[2]; pBhi[buf][2 * jp + 1][1] = r[3];
            ldsm_x4(r, sb + OFF_WLO + boff);
            pBlo[buf][2 * jp][0] = r[0]; pBlo[buf][2 * jp][1] = r[1];
            pBlo[buf][2 * jp + 1][0] = r[2]; pBlo[buf][2 * jp + 1][1] = r[3];
        }
    };
    auto mma_frags = [&](int buf) {
#pragma unroll
        for (int ma = 0; ma < 2; ma++) {
#pragma unroll
            for (int j = 0; j < 4; j++) {
                mma_bf16(acc[ma][j], pAhi[buf][ma], pBhi[buf][j]);
                mma_bf16(acc[ma][j], pAhi[buf][ma], pBlo[buf][j]);
                mma_bf16(acc[ma][j], pAlo[buf][ma], pBhi[buf][j]);
            }
        }
    };

    // ---- issue ALL global loads up front (max MLP, single DRAM exposure) --
    float4 Xv0[4], Xv1[4], Wv0[4], Wv1[4];
#pragma unroll
    for (int i = 0; i < 4; i++) {
        int idx = tid + i * THREADS;
        int row = idx >> 4;
        int c4  = idx & 15;
        Xv0[i] = x4[row * 32 + c4];
        Xv1[i] = x4[row * 32 + c4 + 16];
    }
#pragma unroll
    for (int i = 0; i < 4; i++) {
        int idx = tid + i * THREADS;
        int row = idx >> 4;
        int c4  = idx & 15;
        int kk  = kb + (row >> 1);
        const float4* src = (const float4*)(((row & 1) ? ga : gp) + (size_t)kk * D_DIM);
        Wv0[i] = src[c4];
        Wv1[i] = src[c4 + 16];
    }

    // ---- Stage A: convert h0 of X and W; full y2 and k-stats from regs ----
#pragma unroll
    for (int i = 0; i < 4; i++) {
        int idx = tid + i * THREADS;
        int row = idx >> 4;
        int c4  = idx & 15;
        uint2 hi, lo;
        cvt4t(Xv0[i], hi, lo);
        uint32_t off = (uint32_t)(row * ROW_BYTES + c4 * 8);
        *(uint2*)(smem + OFF_XHI + off) = hi;
        *(uint2*)(smem + OFF_XLO + off) = lo;

        float4 a = Xv0[i], b = Xv1[i];
        float s = fmaf(a.x, a.x, fmaf(a.y, a.y, fmaf(a.z, a.z, a.w * a.w)));
        s = fmaf(b.x, b.x, fmaf(b.y, b.y, fmaf(b.z, b.z, fmaf(b.w, b.w, s))));
        s += __shfl_xor_sync(0xffffffffu, s, 1);
        s += __shfl_xor_sync(0xffffffffu, s, 2);
        s += __shfl_xor_sync(0xffffffffu, s, 4);
        s += __shfl_xor_sync(0xffffffffu, s, 8);
        if ((lane & 15) == 0) y2s[row] = s;
    }
#pragma unroll
    for (int i = 0; i < 4; i++) {
        int idx = tid + i * THREADS;
        int row = idx >> 4;
        int c4  = idx & 15;
        uint2 hi, lo;
        cvt4t(Wv0[i], hi, lo);
        uint32_t off = (uint32_t)(row * ROW_BYTES + c4 * 8);
        *(uint2*)(smem + OFF_WHI + off) = hi;
        *(uint2*)(smem + OFF_WLO + off) = lo;
    }

    // per-k stats from W registers (p in lanes 0-15, a in 16-31)
#pragma unroll
    for (int i = 0; i < 4; i++) {
        float4 a = Wv0[i], b = Wv1[i];
        float s = fmaf(a.x, a.x, fmaf(a.y, a.y, fmaf(a.z, a.z, a.w * a.w)));
        s = fmaf(b.x, b.x, fmaf(b.y, b.y, fmaf(b.z, b.z, fmaf(b.w, b.w, s))));
        float q0 = __shfl_xor_sync(0xffffffffu, a.x, 16);
        float q1 = __shfl_xor_sync(0xffffffffu, a.y, 16);
        float q2 = __shfl_xor_sync(0xffffffffu, a.z, 16);
        float q3 = __shfl_xor_sync(0xffffffffu, a.w, 16);
        float r0 = __shfl_xor_sync(0xffffffffu, b.x, 16);
        float r1 = __shfl_xor_sync(0xffffffffu, b.y, 16);
        float r2 = __shfl_xor_sync(0xffffffffu, b.z, 16);
        float r3 = __shfl_xor_sync(0xffffffffu, b.w, 16);
        float pa = fmaf(a.x, q0, fmaf(a.y, q1, fmaf(a.z, q2, a.w * q3)));
        pa = fmaf(b.x, r0, fmaf(b.y, r1, fmaf(b.z, r2, fmaf(b.w, r3, pa))));
        s  += __shfl_xor_sync(0xffffffffu, s, 1);
        s  += __shfl_xor_sync(0xffffffffu, s, 2);
        s  += __shfl_xor_sync(0xffffffffu, s, 4);
        s  += __shfl_xor_sync(0xffffffffu, s, 8);
        pa += __shfl_xor_sync(0xffffffffu, pa, 1);
        pa += __shfl_xor_sync(0xffffffffu, pa, 2);
        pa += __shfl_xor_sync(0xffffffffu, pa, 4);
        pa += __shfl_xor_sync(0xffffffffu, pa, 8);
        float s_opp = __shfl_xor_sync(0xffffffffu, s, 16);   // a2 -> low lanes
        if (lane == 0) {
            int k = wid + 16 * i;
            float p2 = s, a2 = s_opp;
            float an = fmaxf(sqrtf(a2), MIN_NORM);
            kst[k] = make_float4(p2, pa, 1.f - p2, 2.f * an);
        }
    }
    __syncthreads();

    // ---- Stage B: k-steps 0..3 (d<64) overlapped with h1 converts ---------
#pragma unroll
    for (int i = 0; i < 4; i++) {
        int idx = tid + i * THREADS;
        int row = idx >> 4;
        int c4  = idx & 15;
        uint2 hi, lo;
        cvt4t(Wv1[i], hi, lo);
        uint32_t off = (uint32_t)(row * ROW_BYTES + c4 * 8 + 128);
        *(uint2*)(smem + OFF_WHI + off) = hi;
        *(uint2*)(smem + OFF_WLO + off) = lo;
    }
    load_frags(0, 0);
    mma_frags(0);
    load_frags(0, 1);
    mma_frags(0);
#pragma unroll
    for (int i = 0; i < 4; i++) {
        int idx = tid + i * THREADS;
        int row = idx >> 4;
        int c4  = idx & 15;
        uint2 hi, lo;
        cvt4t(Xv1[i], hi, lo);
        uint32_t off = (uint32_t)(row * ROW_BYTES + c4 * 8 + 128);
        *(uint2*)(smem + OFF_XHI + off) = hi;
        *(uint2*)(smem + OFF_XLO + off) = lo;
    }
    load_frags(0, 2);
    load_frags(1, 3);           // start double-buffering
    mma_frags(0);
    mma_frags(1);
    __syncthreads();

    // ---- Stage C: k-steps 4..7 software-pipelined -------------------------
    load_frags(0, 4);
    load_frags(1, 5);
    mma_frags(0);
    load_frags(0, 6);
    mma_frags(1);
    load_frags(1, 7);
    // prefetch epilogue scalars while final mmas run
    const int l4 = lane >> 2;
    const int lm = lane & 3;
    const float y20 = y2s[rm + l4];
    const float y21 = y2s[rm + l4 + 8];
    mma_frags(0);
    float4 kc[4];
#pragma unroll
    for (int j = 0; j < 4; j++) kc[j] = kst[wn * 16 + j * 4 + lm];
    mma_frags(1);

    // ---- epilogue ----------------------------------------------------------
#pragma unroll
    for (int ma = 0; ma < 2; ma++) {
        const int r0 = rm + ma * 16 + l4;
        const int r1 = r0 + 8;
        const float ya = (ma == 0) ? y20 : y2s[r0];
        const float yb = (ma == 0) ? y21 : y2s[r1];
        float* o0 = out + (size_t)(bb + r0) * K_COLS + kb;
        float* o1 = out + (size_t)(bb + r1) * K_COLS + kb;
#pragma unroll
        for (int j = 0; j < 4; j++) {
            const int kl = wn * 16 + j * 4 + lm;
            o0[kl] = mobius_epi(acc[ma][j][0], acc[ma][j][1], ya, kc[j]);
            o1[kl] = mobius_epi(acc[ma][j][2], acc[ma][j][3], yb, kc[j]);
        }
    }
}

// ---------------------------------------------------------------------------
extern "C" void kernel_launch(void* const* d_in, const int* in_sizes, int n_in,
                              void* d_out, int out_size) {
    const float* x = (const float*)d_in[0];   // (4096, 128)
    const float* p = (const float*)d_in[1];   // (256, 128)
    const float* a = (const float*)d_in[2];   // (256, 128)
    float* out = (float*)d_out;               // (4096, 256)

    cudaFuncSetAttribute(mobius_mlr_mma_kernel,
                         cudaFuncAttributeMaxDynamicSharedMemorySize, SMEM_BYTES);

    dim3 grid(K_COLS / BKH, B_ROWS / BM);     // (4, 32) = 128 CTAs, one wave
    mobius_mlr_mma_kernel<<<grid, THREADS, SMEM_BYTES>>>(x, p, a, out);
}

// round 16
// speedup vs baseline: 1.3964x; 1.1805x over previous
#include <cuda_runtime.h>
#include <cuda_fp16.h>
#include <math.h>
#include <cstdint>

#define B_ROWS 4096
#define K_COLS 256
#define D_DIM  128
#define BM     128       // x-rows per CTA
#define BKH    64        // hyperplanes per CTA (=> 128 interleaved W rows)
#define THREADS 512
#define MIN_NORM 1e-15f

#define SCALE    64.f
#define INV_S2   (1.f / 4096.f)     // 1/(64*64), applied to accumulators

#define TSTRIDE 136      // fp16 elems per tile row (272 B), conflict-free ldmatrix
#define ROW_BYTES (TSTRIDE * 2)
#define TILE_BYTES (128 * ROW_BYTES)

// smem byte offsets (three tiles: Xhi, Xlo, Whi)
#define OFF_Y2   0                       // 128 f32
#define OFF_KST  512                     // 64 x float4 {p2, pa, beta, 2an}
#define OFF_XHI  2048
#define OFF_XLO  (OFF_XHI + TILE_BYTES)
#define OFF_WHI  (OFF_XLO + TILE_BYTES)
#define SMEM_BYTES (OFF_WHI + TILE_BYTES)   // ~106.5 KB

// ---------------------------------------------------------------------------
__device__ __forceinline__ uint32_t smem_u32(const void* p) {
    uint32_t a;
    asm("{ .reg .u64 t; cvta.to.shared.u64 t, %1; cvt.u32.u64 %0, t; }"
        : "=r"(a) : "l"(p));
    return a;
}

__device__ __forceinline__ void ldsm_x4(uint32_t* r, uint32_t addr) {
    asm volatile("ldmatrix.sync.aligned.m8n8.x4.shared.b16 {%0,%1,%2,%3}, [%4];"
                 : "=r"(r[0]), "=r"(r[1]), "=r"(r[2]), "=r"(r[3]) : "r"(addr));
}

__device__ __forceinline__ void mma_f16(float* c, const uint32_t* a, const uint32_t* b) {
    asm volatile(
        "mma.sync.aligned.m16n8k16.row.col.f32.f16.f16.f32 "
        "{%0,%1,%2,%3}, {%4,%5,%6,%7}, {%8,%9}, {%0,%1,%2,%3};"
        : "+f"(c[0]), "+f"(c[1]), "+f"(c[2]), "+f"(c[3])
        : "r"(a[0]), "r"(a[1]), "r"(a[2]), "r"(a[3]), "r"(b[0]), "r"(b[1]));
}

// fp32x4 -> scaled fp16 hi + fp16 lo (RN both steps)
__device__ __forceinline__ void cvt4x(const float4 v, uint2& hi, uint2& lo) {
    float2 s0 = make_float2(v.x * SCALE, v.y * SCALE);
    float2 s1 = make_float2(v.z * SCALE, v.w * SCALE);
    __half2 h0 = __float22half2_rn(s0);
    __half2 h1 = __float22half2_rn(s1);
    hi.x = *(uint32_t*)&h0;
    hi.y = *(uint32_t*)&h1;
    float2 f0 = __half22float2(h0);
    float2 f1 = __half22float2(h1);
    __half2 l0 = __float22half2_rn(make_float2(s0.x - f0.x, s0.y - f0.y));
    __half2 l1 = __float22half2_rn(make_float2(s1.x - f1.x, s1.y - f1.y));
    lo.x = *(uint32_t*)&l0;
    lo.y = *(uint32_t*)&l1;
}

// fp32x4 -> scaled fp16 hi only (for W)
__device__ __forceinline__ void cvt4w(const float4 v, uint2& hi) {
    __half2 h0 = __float22half2_rn(make_float2(v.x * SCALE, v.y * SCALE));
    __half2 h1 = __float22half2_rn(make_float2(v.z * SCALE, v.w * SCALE));
    hi.x = *(uint32_t*)&h0;
    hi.y = *(uint32_t*)&h1;
}

// fast asinh: sign * log(|z| + sqrt(z^2+1))
__device__ __forceinline__ float fast_asinh(float z) {
    float az = fabsf(z);
    float u  = fmaf(az, az, 1.f);
    float t;
    asm("sqrt.approx.f32 %0, %1;" : "=f"(t) : "f"(u));
    float r = __logf(az + t);
    return copysignf(r, z);
}

// single-division Mobius epilogue; kc = {p2, pa, beta, 2an}
__device__ __forceinline__ float mobius_epi(float px, float xa, float y2, float4 kc) {
    const float p2 = kc.x, pa = kc.y, beta = kc.z, an2 = kc.w;
    float t     = fmaf(-2.f, px, 1.f);          // 1 - 2px
    float alpha = t + y2;
    float den   = fmaf(p2, y2, t);              // den_m
    float num   = fmaf(beta, xa, -alpha * pa);  // beta*xa - alpha*pa
    float b2y2  = beta * beta * y2;
    float e2    = fmaf(alpha * p2, alpha, b2y2);
    float e3    = fmaf(-beta, t, beta);         // 2*beta*px
    float ms2   = fmaf(-alpha, e3, e2);
    float g     = fmaf(den, den, -ms2);
    float dn    = fmaxf(an2 * g, MIN_NORM);
    float z     = __fdividef(4.f * num * den, dn);
    return an2 * fast_asinh(z);
}

// ---------------------------------------------------------------------------
extern __shared__ char smem[];

__global__ void __launch_bounds__(THREADS, 1)
mobius_mlr_mma_kernel(const float* __restrict__ x,
                      const float* __restrict__ gp,
                      const float* __restrict__ ga,
                      float* __restrict__ out) {
    const uint32_t sb  = smem_u32(smem);
    const int tid  = threadIdx.x;
    const int wid  = tid >> 5;
    const int lane = tid & 31;
    const int kb   = blockIdx.x * BKH;
    const int bb   = blockIdx.y * BM;

    float*  y2s = (float*)(smem + OFF_Y2);
    float4* kst = (float4*)(smem + OFF_KST);

    const float4* x4 = (const float4*)(x + (size_t)bb * D_DIM);

    // warp tiling constants (16 warps, warp tile 32 rows x 32 W-cols)
    const int wm = wid & 3;
    const int wn = wid >> 2;
    const int rm = wm * 32;
    const int cn = wn * 32;

    const int a_row = lane & 15;
    const int a_kh  = (lane >> 4) * 8;
    const int b_g   = lane >> 3;
    const int b_row = lane & 7;
    const int b_joff = (b_g >> 1);
    const int b_kh  = (b_g & 1) * 8;

    float acc[2][4][4];
#pragma unroll
    for (int ma = 0; ma < 2; ma++)
#pragma unroll
        for (int j = 0; j < 4; j++)
#pragma unroll
            for (int q = 0; q < 4; q++) acc[ma][j][q] = 0.f;

    // one mma k-step: A hi+lo, B hi only -> 16 HMMA
    auto do_kstep = [&](int ks) {
        const int kk = ks * 16;
        uint32_t Ahi[2][4], Alo[2][4], Bhi[4][2];
#pragma unroll
        for (int ma = 0; ma < 2; ma++) {
            uint32_t aoff = (uint32_t)((rm + ma * 16 + a_row) * ROW_BYTES
                                       + (kk + a_kh) * 2);
            ldsm_x4(Ahi[ma], sb + OFF_XHI + aoff);
            ldsm_x4(Alo[ma], sb + OFF_XLO + aoff);
        }
#pragma unroll
        for (int jp = 0; jp < 2; jp++) {
            uint32_t boff = (uint32_t)((cn + (2 * jp + b_joff) * 8 + b_row) * ROW_BYTES
                                       + (kk + b_kh) * 2);
            uint32_t r[4];
            ldsm_x4(r, sb + OFF_WHI + boff);
            Bhi[2 * jp][0] = r[0]; Bhi[2 * jp][1] = r[1];
            Bhi[2 * jp + 1][0] = r[2]; Bhi[2 * jp + 1][1] = r[3];
        }
#pragma unroll
        for (int ma = 0; ma < 2; ma++) {
#pragma unroll
            for (int j = 0; j < 4; j++) {
                mma_f16(acc[ma][j], Ahi[ma], Bhi[j]);
                mma_f16(acc[ma][j], Alo[ma], Bhi[j]);
            }
        }
    };

    // ---- issue ALL global loads up front (max MLP, single DRAM exposure) --
    float4 Xv0[4], Xv1[4], Wv0[4], Wv1[4];
#pragma unroll
    for (int i = 0; i < 4; i++) {
        int idx = tid + i * THREADS;
        int row = idx >> 4;
        int c4  = idx & 15;
        Xv0[i] = x4[row * 32 + c4];
        Xv1[i] = x4[row * 32 + c4 + 16];
    }
#pragma unroll
    for (int i = 0; i < 4; i++) {
        int idx = tid + i * THREADS;
        int row = idx >> 4;
        int c4  = idx & 15;
        int kk  = kb + (row >> 1);
        const float4* src = (const float4*)(((row & 1) ? ga : gp) + (size_t)kk * D_DIM);
        Wv0[i] = src[c4];
        Wv1[i] = src[c4 + 16];
    }

    // ---- Stage A: convert h0 of X and W; full y2 and k-stats from regs ----
#pragma unroll
    for (int i = 0; i < 4; i++) {
        int idx = tid + i * THREADS;
        int row = idx >> 4;
        int c4  = idx & 15;
        uint2 hi, lo;
        cvt4x(Xv0[i], hi, lo);
        uint32_t off = (uint32_t)(row * ROW_BYTES + c4 * 8);
        *(uint2*)(smem + OFF_XHI + off) = hi;
        *(uint2*)(smem + OFF_XLO + off) = lo;

        float4 a = Xv0[i], b = Xv1[i];
        float s = fmaf(a.x, a.x, fmaf(a.y, a.y, fmaf(a.z, a.z, a.w * a.w)));
        s = fmaf(b.x, b.x, fmaf(b.y, b.y, fmaf(b.z, b.z, fmaf(b.w, b.w, s))));
        s += __shfl_xor_sync(0xffffffffu, s, 1);
        s += __shfl_xor_sync(0xffffffffu, s, 2);
        s += __shfl_xor_sync(0xffffffffu, s, 4);
        s += __shfl_xor_sync(0xffffffffu, s, 8);
        if ((lane & 15) == 0) y2s[row] = s;
    }
#pragma unroll
    for (int i = 0; i < 4; i++) {
        int idx = tid + i * THREADS;
        int row = idx >> 4;
        int c4  = idx & 15;
        uint2 hi;
        cvt4w(Wv0[i], hi);
        uint32_t off = (uint32_t)(row * ROW_BYTES + c4 * 8);
        *(uint2*)(smem + OFF_WHI + off) = hi;
    }

    // per-k stats from W registers (p in lanes 0-15, a in 16-31), exact fp32
#pragma unroll
    for (int i = 0; i < 4; i++) {
        float4 a = Wv0[i], b = Wv1[i];
        float s = fmaf(a.x, a.x, fmaf(a.y, a.y, fmaf(a.z, a.z, a.w * a.w)));
        s = fmaf(b.x, b.x, fmaf(b.y, b.y, fmaf(b.z, b.z, fmaf(b.w, b.w, s))));
        float q0 = __shfl_xor_sync(0xffffffffu, a.x, 16);
        float q1 = __shfl_xor_sync(0xffffffffu, a.y, 16);
        float q2 = __shfl_xor_sync(0xffffffffu, a.z, 16);
        float q3 = __shfl_xor_sync(0xffffffffu, a.w, 16);
        float r0 = __shfl_xor_sync(0xffffffffu, b.x, 16);
        float r1 = __shfl_xor_sync(0xffffffffu, b.y, 16);
        float r2 = __shfl_xor_sync(0xffffffffu, b.z, 16);
        float r3 = __shfl_xor_sync(0xffffffffu, b.w, 16);
        float pa = fmaf(a.x, q0, fmaf(a.y, q1, fmaf(a.z, q2, a.w * q3)));
        pa = fmaf(b.x, r0, fmaf(b.y, r1, fmaf(b.z, r2, fmaf(b.w, r3, pa))));
        s  += __shfl_xor_sync(0xffffffffu, s, 1);
        s  += __shfl_xor_sync(0xffffffffu, s, 2);
        s  += __shfl_xor_sync(0xffffffffu, s, 4);
        s  += __shfl_xor_sync(0xffffffffu, s, 8);
        pa += __shfl_xor_sync(0xffffffffu, pa, 1);
        pa += __shfl_xor_sync(0xffffffffu, pa, 2);
        pa += __shfl_xor_sync(0xffffffffu, pa, 4);
        pa += __shfl_xor_sync(0xffffffffu, pa, 8);
        float s_opp = __shfl_xor_sync(0xffffffffu, s, 16);   // a2 -> low lanes
        if (lane == 0) {
            int k = wid + 16 * i;
            float p2 = s, a2 = s_opp;
            float an = fmaxf(sqrtf(a2), MIN_NORM);
            kst[k] = make_float4(p2, pa, 1.f - p2, 2.f * an);
        }
    }
    __syncthreads();

    // ---- Stage B: k-steps 0..3 (d<64) overlapped with h1 converts ---------
#pragma unroll
    for (int i = 0; i < 4; i++) {
        int idx = tid + i * THREADS;
        int row = idx >> 4;
        int c4  = idx & 15;
        uint2 hi;
        cvt4w(Wv1[i], hi);
        uint32_t off = (uint32_t)(row * ROW_BYTES + c4 * 8 + 128);
        *(uint2*)(smem + OFF_WHI + off) = hi;
    }
    do_kstep(0);
    do_kstep(1);
#pragma unroll
    for (int i = 0; i < 4; i++) {
        int idx = tid + i * THREADS;
        int row = idx >> 4;
        int c4  = idx & 15;
        uint2 hi, lo;
        cvt4x(Xv1[i], hi, lo);
        uint32_t off = (uint32_t)(row * ROW_BYTES + c4 * 8 + 128);
        *(uint2*)(smem + OFF_XHI + off) = hi;
        *(uint2*)(smem + OFF_XLO + off) = lo;
    }
    do_kstep(2);
    do_kstep(3);
    __syncthreads();

    // ---- Stage C: k-steps 4..7 + epilogue ---------------------------------
    do_kstep(4);
    do_kstep(5);
    do_kstep(6);
    do_kstep(7);

    const int l4 = lane >> 2;
    const int lm = lane & 3;
#pragma unroll
    for (int ma = 0; ma < 2; ma++) {
        const int r0 = rm + ma * 16 + l4;
        const int r1 = r0 + 8;
        const float y20 = y2s[r0];
        const float y21 = y2s[r1];
        float* o0 = out + (size_t)(bb + r0) * K_COLS + kb;
        float* o1 = out + (size_t)(bb + r1) * K_COLS + kb;
#pragma unroll
        for (int j = 0; j < 4; j++) {
            const int kl = wn * 16 + j * 4 + lm;
            const float4 kc = kst[kl];
            o0[kl] = mobius_epi(acc[ma][j][0] * INV_S2, acc[ma][j][1] * INV_S2, y20, kc);
            o1[kl] = mobius_epi(acc[ma][j][2] * INV_S2, acc[ma][j][3] * INV_S2, y21, kc);
        }
    }
}

// ---------------------------------------------------------------------------
extern "C" void kernel_launch(void* const* d_in, const int* in_sizes, int n_in,
                              void* d_out, int out_size) {
    const float* x = (const float*)d_in[0];   // (4096, 128)
    const float* p = (const float*)d_in[1];   // (256, 128)
    const float* a = (const float*)d_in[2];   // (256, 128)
    float* out = (float*)d_out;               // (4096, 256)

    cudaFuncSetAttribute(mobius_mlr_mma_kernel,
                         cudaFuncAttributeMaxDynamicSharedMemorySize, SMEM_BYTES);

    dim3 grid(K_COLS / BKH, B_ROWS / BM);     // (4, 32) = 128 CTAs, one wave
    mobius_mlr_mma_kernel<<<grid, THREADS, SMEM_BYTES>>>(x, p, a, out);
}

// round 17
// speedup vs baseline: 1.4090x; 1.0090x over previous
#include <cuda_runtime.h>
#include <cuda_fp16.h>
#include <math.h>
#include <cstdint>

#define B_ROWS 4096
#define K_COLS 256
#define D_DIM  128
#define BM     128       // x-rows per CTA
#define BKH    64        // hyperplanes per CTA (=> 128 interleaved W rows)
#define THREADS 512
#define MIN_NORM 1e-15f

#define SCALE    64.f
#define INV_S2   (1.f / 4096.f)     // 1/(64*64), applied to accumulators

#define TSTRIDE 136      // fp16 elems per tile row (272 B), conflict-free ldmatrix
#define ROW_BYTES (TSTRIDE * 2)
#define TILE_BYTES (128 * ROW_BYTES)

// smem byte offsets (two tiles: Xhi, Whi)
#define OFF_Y2   0                       // 128 f32
#define OFF_KST  512                     // 64 x float4 {p2, pa, beta, 2an}
#define OFF_XHI  2048
#define OFF_WHI  (OFF_XHI + TILE_BYTES)
#define SMEM_BYTES (OFF_WHI + TILE_BYTES)   // ~71.5 KB

// ---------------------------------------------------------------------------
__device__ __forceinline__ uint32_t smem_u32(const void* p) {
    uint32_t a;
    asm("{ .reg .u64 t; cvta.to.shared.u64 t, %1; cvt.u32.u64 %0, t; }"
        : "=r"(a) : "l"(p));
    return a;
}

__device__ __forceinline__ void ldsm_x4(uint32_t* r, uint32_t addr) {
    asm volatile("ldmatrix.sync.aligned.m8n8.x4.shared.b16 {%0,%1,%2,%3}, [%4];"
                 : "=r"(r[0]), "=r"(r[1]), "=r"(r[2]), "=r"(r[3]) : "r"(addr));
}

__device__ __forceinline__ void mma_f16(float* c, const uint32_t* a, const uint32_t* b) {
    asm volatile(
        "mma.sync.aligned.m16n8k16.row.col.f32.f16.f16.f32 "
        "{%0,%1,%2,%3}, {%4,%5,%6,%7}, {%8,%9}, {%0,%1,%2,%3};"
        : "+f"(c[0]), "+f"(c[1]), "+f"(c[2]), "+f"(c[3])
        : "r"(a[0]), "r"(a[1]), "r"(a[2]), "r"(a[3]), "r"(b[0]), "r"(b[1]));
}

// fp32x4 -> scaled fp16 (RN)
__device__ __forceinline__ void cvt4h(const float4 v, uint2& hi) {
    __half2 h0 = __float22half2_rn(make_float2(v.x * SCALE, v.y * SCALE));
    __half2 h1 = __float22half2_rn(make_float2(v.z * SCALE, v.w * SCALE));
    hi.x = *(uint32_t*)&h0;
    hi.y = *(uint32_t*)&h1;
}

// fast asinh: sign * log(|z| + sqrt(z^2+1))
__device__ __forceinline__ float fast_asinh(float z) {
    float az = fabsf(z);
    float u  = fmaf(az, az, 1.f);
    float t;
    asm("sqrt.approx.f32 %0, %1;" : "=f"(t) : "f"(u));
    float r = __logf(az + t);
    return copysignf(r, z);
}

// single-division Mobius epilogue; kc = {p2, pa, beta, 2an}
__device__ __forceinline__ float mobius_epi(float px, float xa, float y2, float4 kc) {
    const float p2 = kc.x, pa = kc.y, beta = kc.z, an2 = kc.w;
    float t     = fmaf(-2.f, px, 1.f);          // 1 - 2px
    float alpha = t + y2;
    float den   = fmaf(p2, y2, t);              // den_m
    float num   = fmaf(beta, xa, -alpha * pa);  // beta*xa - alpha*pa
    float b2y2  = beta * beta * y2;
    float e2    = fmaf(alpha * p2, alpha, b2y2);
    float e3    = fmaf(-beta, t, beta);         // 2*beta*px
    float ms2   = fmaf(-alpha, e3, e2);
    float g     = fmaf(den, den, -ms2);
    float dn    = fmaxf(an2 * g, MIN_NORM);
    float z     = __fdividef(4.f * num * den, dn);
    return an2 * fast_asinh(z);
}

// ---------------------------------------------------------------------------
extern __shared__ char smem[];

__global__ void __launch_bounds__(THREADS, 1)
mobius_mlr_mma_kernel(const float* __restrict__ x,
                      const float* __restrict__ gp,
                      const float* __restrict__ ga,
                      float* __restrict__ out) {
    const uint32_t sb  = smem_u32(smem);
    const int tid  = threadIdx.x;
    const int wid  = tid >> 5;
    const int lane = tid & 31;
    const int kb   = blockIdx.x * BKH;
    const int bb   = blockIdx.y * BM;

    float*  y2s = (float*)(smem + OFF_Y2);
    float4* kst = (float4*)(smem + OFF_KST);

    const float4* x4 = (const float4*)(x + (size_t)bb * D_DIM);

    // warp tiling constants (16 warps, warp tile 32 rows x 32 W-cols)
    const int wm = wid & 3;
    const int wn = wid >> 2;
    const int rm = wm * 32;
    const int cn = wn * 32;

    const int a_row = lane & 15;
    const int a_kh  = (lane >> 4) * 8;
    const int b_g   = lane >> 3;
    const int b_row = lane & 7;
    const int b_joff = (b_g >> 1);
    const int b_kh  = (b_g & 1) * 8;

    float acc[2][4][4];
#pragma unroll
    for (int ma = 0; ma < 2; ma++)
#pragma unroll
        for (int j = 0; j < 4; j++)
#pragma unroll
            for (int q = 0; q < 4; q++) acc[ma][j][q] = 0.f;

    // one mma k-step: A hi, B hi -> 8 HMMA, 4 LDSM
    auto do_kstep = [&](int ks) {
        const int kk = ks * 16;
        uint32_t Ahi[2][4], Bhi[4][2];
#pragma unroll
        for (int ma = 0; ma < 2; ma++) {
            uint32_t aoff = (uint32_t)((rm + ma * 16 + a_row) * ROW_BYTES
                                       + (kk + a_kh) * 2);
            ldsm_x4(Ahi[ma], sb + OFF_XHI + aoff);
        }
#pragma unroll
        for (int jp = 0; jp < 2; jp++) {
            uint32_t boff = (uint32_t)((cn + (2 * jp + b_joff) * 8 + b_row) * ROW_BYTES
                                       + (kk + b_kh) * 2);
            uint32_t r[4];
            ldsm_x4(r, sb + OFF_WHI + boff);
            Bhi[2 * jp][0] = r[0]; Bhi[2 * jp][1] = r[1];
            Bhi[2 * jp + 1][0] = r[2]; Bhi[2 * jp + 1][1] = r[3];
        }
#pragma unroll
        for (int ma = 0; ma < 2; ma++) {
#pragma unroll
            for (int j = 0; j < 4; j++) {
                mma_f16(acc[ma][j], Ahi[ma], Bhi[j]);
            }
        }
    };

    // ---- issue ALL global loads up front (max MLP, single DRAM exposure) --
    float4 Xv0[4], Xv1[4], Wv0[4], Wv1[4];
#pragma unroll
    for (int i = 0; i < 4; i++) {
        int idx = tid + i * THREADS;
        int row = idx >> 4;
        int c4  = idx & 15;
        Xv0[i] = x4[row * 32 + c4];
        Xv1[i] = x4[row * 32 + c4 + 16];
    }
#pragma unroll
    for (int i = 0; i < 4; i++) {
        int idx = tid + i * THREADS;
        int row = idx >> 4;
        int c4  = idx & 15;
        int kk  = kb + (row >> 1);
        const float4* src = (const float4*)(((row & 1) ? ga : gp) + (size_t)kk * D_DIM);
        Wv0[i] = src[c4];
        Wv1[i] = src[c4 + 16];
    }

    // ---- Stage A: convert h0 of X and W; full y2 and k-stats from regs ----
#pragma unroll
    for (int i = 0; i < 4; i++) {
        int idx = tid + i * THREADS;
        int row = idx >> 4;
        int c4  = idx & 15;
        uint2 hi;
        cvt4h(Xv0[i], hi);
        uint32_t off = (uint32_t)(row * ROW_BYTES + c4 * 8);
        *(uint2*)(smem + OFF_XHI + off) = hi;

        float4 a = Xv0[i], b = Xv1[i];
        float s = fmaf(a.x, a.x, fmaf(a.y, a.y, fmaf(a.z, a.z, a.w * a.w)));
        s = fmaf(b.x, b.x, fmaf(b.y, b.y, fmaf(b.z, b.z, fmaf(b.w, b.w, s))));
        s += __shfl_xor_sync(0xffffffffu, s, 1);
        s += __shfl_xor_sync(0xffffffffu, s, 2);
        s += __shfl_xor_sync(0xffffffffu, s, 4);
        s += __shfl_xor_sync(0xffffffffu, s, 8);
        if ((lane & 15) == 0) y2s[row] = s;
    }
#pragma unroll
    for (int i = 0; i < 4; i++) {
        int idx = tid + i * THREADS;
        int row = idx >> 4;
        int c4  = idx & 15;
        uint2 hi;
        cvt4h(Wv0[i], hi);
        uint32_t off = (uint32_t)(row * ROW_BYTES + c4 * 8);
        *(uint2*)(smem + OFF_WHI + off) = hi;
    }

    // per-k stats from W registers (p in lanes 0-15, a in 16-31), exact fp32
#pragma unroll
    for (int i = 0; i < 4; i++) {
        float4 a = Wv0[i], b = Wv1[i];
        float s = fmaf(a.x, a.x, fmaf(a.y, a.y, fmaf(a.z, a.z, a.w * a.w)));
        s = fmaf(b.x, b.x, fmaf(b.y, b.y, fmaf(b.z, b.z, fmaf(b.w, b.w, s))));
        float q0 = __shfl_xor_sync(0xffffffffu, a.x, 16);
        float q1 = __shfl_xor_sync(0xffffffffu, a.y, 16);
        float q2 = __shfl_xor_sync(0xffffffffu, a.z, 16);
        float q3 = __shfl_xor_sync(0xffffffffu, a.w, 16);
        float r0 = __shfl_xor_sync(0xffffffffu, b.x, 16);
        float r1 = __shfl_xor_sync(0xffffffffu, b.y, 16);
        float r2 = __shfl_xor_sync(0xffffffffu, b.z, 16);
        float r3 = __shfl_xor_sync(0xffffffffu, b.w, 16);
        float pa = fmaf(a.x, q0, fmaf(a.y, q1, fmaf(a.z, q2, a.w * q3)));
        pa = fmaf(b.x, r0, fmaf(b.y, r1, fmaf(b.z, r2, fmaf(b.w, r3, pa))));
        s  += __shfl_xor_sync(0xffffffffu, s, 1);
        s  += __shfl_xor_sync(0xffffffffu, s, 2);
        s  += __shfl_xor_sync(0xffffffffu, s, 4);
        s  += __shfl_xor_sync(0xffffffffu, s, 8);
        pa += __shfl_xor_sync(0xffffffffu, pa, 1);
        pa += __shfl_xor_sync(0xffffffffu, pa, 2);
        pa += __shfl_xor_sync(0xffffffffu, pa, 4);
        pa += __shfl_xor_sync(0xffffffffu, pa, 8);
        float s_opp = __shfl_xor_sync(0xffffffffu, s, 16);   // a2 -> low lanes
        if (lane == 0) {
            int k = wid + 16 * i;
            float p2 = s, a2 = s_opp;
            float an = fmaxf(sqrtf(a2), MIN_NORM);
            kst[k] = make_float4(p2, pa, 1.f - p2, 2.f * an);
        }
    }
    __syncthreads();

    // ---- Stage B: k-steps 0..3 (d<64) overlapped with h1 converts ---------
#pragma unroll
    for (int i = 0; i < 4; i++) {
        int idx = tid + i * THREADS;
        int row = idx >> 4;
        int c4  = idx & 15;
        uint2 hi;
        cvt4h(Wv1[i], hi);
        uint32_t off = (uint32_t)(row * ROW_BYTES + c4 * 8 + 128);
        *(uint2*)(smem + OFF_WHI + off) = hi;
    }
    do_kstep(0);
    do_kstep(1);
#pragma unroll
    for (int i = 0; i < 4; i++) {
        int idx = tid + i * THREADS;
        int row = idx >> 4;
        int c4  = idx & 15;
        uint2 hi;
        cvt4h(Xv1[i], hi);
        uint32_t off = (uint32_t)(row * ROW_BYTES + c4 * 8 + 128);
        *(uint2*)(smem + OFF_XHI + off) = hi;
    }
    do_kstep(2);
    do_kstep(3);
    __syncthreads();

    // ---- Stage C: k-steps 4..7 + epilogue ---------------------------------
    do_kstep(4);
    do_kstep(5);
    do_kstep(6);
    do_kstep(7);

    const int l4 = lane >> 2;
    const int lm = lane & 3;
#pragma unroll
    for (int ma = 0; ma < 2; ma++) {
        const int r0 = rm + ma * 16 + l4;
        const int r1 = r0 + 8;
        const float y20 = y2s[r0];
        const float y21 = y2s[r1];
        float* o0 = out + (size_t)(bb + r0) * K_COLS + kb;
        float* o1 = out + (size_t)(bb + r1) * K_COLS + kb;
#pragma unroll
        for (int j = 0; j < 4; j++) {
            const int kl = wn * 16 + j * 4 + lm;
            const float4 kc = kst[kl];
            o0[kl] = mobius_epi(acc[ma][j][0] * INV_S2, acc[ma][j][1] * INV_S2, y20, kc);
            o1[kl] = mobius_epi(acc[ma][j][2] * INV_S2, acc[ma][j][3] * INV_S2, y21, kc);
        }
    }
}

// ---------------------------------------------------------------------------
extern "C" void kernel_launch(void* const* d_in, const int* in_sizes, int n_in,
                              void* d_out, int out_size) {
    const float* x = (const float*)d_in[0];   // (4096, 128)
    const float* p = (const float*)d_in[1];   // (256, 128)
    const float* a = (const float*)d_in[2];   // (256, 128)
    float* out = (float*)d_out;               // (4096, 256)

    cudaFuncSetAttribute(mobius_mlr_mma_kernel,
                         cudaFuncAttributeMaxDynamicSharedMemorySize, SMEM_BYTES);

    dim3 grid(K_COLS / BKH, B_ROWS / BM);     // (4, 32) = 128 CTAs, one wave
    mobius_mlr_mma_kernel<<<grid, THREADS, SMEM_BYTES>>>(x, p, a, out);
}